// round 13
// baseline (speedup 1.0000x reference)
#include <cuda_runtime.h>
#include <cstdint>

// Batched NT-GEMM: C[b,i,j] = sum_d A[b,i,d] * B[b,j,d]
// B=8, M=N=4096, K=128, fp32 in/out.
//
// tf32 mma.sync.m16n8k8 path.  Phase 1: prepass -> fragment-major tf32 scratch.
// Phase 2: 256x128-tile GEMM (512 thr, 1 CTA/SM, full RF), all-K prefetch into
// 4 smem stages (192KB) via cp.async; 4 bar.sync per CTA.
// Tile growth cuts L2 operand traffic 2.1GB -> 0.79GB (below tensor floor).

#define BATCH 8
#define MDIM 4096
#define NDIM 4096
#define KDIM 128

#define TILE_M 256
#define TILE_N 128
#define NCHUNKS 4          // K chunks of 32 (4 kt-groups of 8)

// Fragment-major scratch:
// Atf: [b][M128(32)][kt(16)][mt(8)][lane(32)][r(4)]   (16.8 MB)
// Btf: [b][N128(32)][kt(16)][nt(16)][lane(32)][r(2)]  (16.8 MB)
__device__ float g_Atf[(size_t)BATCH * MDIM * KDIM];
__device__ float g_Btf[(size_t)BATCH * NDIM * KDIM];

// Smem stage: A 8192 floats [kt4][mt16][lane32][r4] (32KB)
//           + B 4096 floats [kt4][nt16][lane32][r2] (16KB) = 48KB; 4 stages.
#define STAGE_FLOATS 12288
#define SMEM_BYTES (NCHUNKS * STAGE_FLOATS * 4)   // 192 KB

__device__ __forceinline__ float f2tf32f(float f) {
    uint32_t u;
    asm("cvt.rna.tf32.f32 %0, %1;" : "=r"(u) : "f"(f));
    return __uint_as_float(u);
}

__device__ __forceinline__ uint32_t smem_u32(const void* p) {
    uint32_t a;
    asm("{ .reg .u64 t; cvta.to.shared.u64 t, %1; cvt.u32.u64 %0, t; }"
        : "=r"(a) : "l"(p));
    return a;
}

// ---------------- Prepass ----------------
__global__ __launch_bounds__(256)
void prep_a_kernel(const float* __restrict__ A) {
    const int id   = blockIdx.x * 256 + threadIdx.x;   // 0 .. 2^20-1
    const int lane = id & 31;
    const int mt   = (id >> 5) & 7;
    const int kt   = (id >> 8) & 15;
    const int M    = (id >> 12) & 31;
    const int b    = id >> 17;

    const int g  = lane >> 2;
    const int tt = lane & 3;
    const int m0 = M * 128 + mt * 16 + g;
    const int k0 = kt * 8 + tt;

    const float* src = A + ((size_t)b * MDIM + m0) * KDIM;
    float4 v;
    v.x = f2tf32f(src[k0]);
    v.y = f2tf32f(src[8 * KDIM + k0]);
    v.z = f2tf32f(src[k0 + 4]);
    v.w = f2tf32f(src[8 * KDIM + k0 + 4]);
    *reinterpret_cast<float4*>(g_Atf + (size_t)id * 4) = v;
}

__global__ __launch_bounds__(256)
void prep_b_kernel(const float* __restrict__ B) {
    const int id   = blockIdx.x * 256 + threadIdx.x;   // 0 .. 2^21-1
    const int lane = id & 31;
    const int nt   = (id >> 5) & 15;
    const int kt   = (id >> 9) & 15;
    const int N    = (id >> 13) & 31;
    const int b    = id >> 18;

    const int g  = lane >> 2;
    const int tt = lane & 3;
    const int n0 = N * 128 + nt * 8 + g;
    const int k0 = kt * 8 + tt;

    const float* src = B + ((size_t)b * NDIM + n0) * KDIM;
    float2 v;
    v.x = f2tf32f(src[k0]);
    v.y = f2tf32f(src[k0 + 4]);
    *reinterpret_cast<float2*>(g_Btf + (size_t)id * 2) = v;
}

// ---------------- Main GEMM: 256x128 tile, 512 threads, 1 CTA/SM ----------------
__global__ __launch_bounds__(512, 1)
void bmm_tf32_big_kernel(float* __restrict__ C) {
    extern __shared__ float sm[];
    const uint32_t smem_base = smem_u32(sm);

    const int tid  = threadIdx.x;
    const int lane = tid & 31;
    const int wid  = tid >> 5;          // 0..15
    const int g    = lane >> 2;
    const int tt   = lane & 3;

    const int b  = blockIdx.z;
    const int by = blockIdx.y;          // M256 tile (0..15)
    const int bx = blockIdx.x;          // N128 tile (0..31)

    // Two consecutive M128 fragment blocks make up this CTA's 256 rows.
    const float* srcA0 = g_Atf + (size_t)((b * 32 + by * 2) * 16) * 1024;
    const float* srcA1 = srcA0 + 16384;
    const float* srcB  = g_Btf + (size_t)((b * 32 + bx) * 16) * 1024;
    float* Cb = C + (size_t)b * MDIM * NDIM;

    const int mband = wid >> 2;         // 0..3  (64-row band)
    const int nband = wid & 3;          // 0..3  (32-col band)

    float acc[4][4][4];
    #pragma unroll
    for (int i = 0; i < 4; i++)
        #pragma unroll
        for (int j = 0; j < 4; j++)
            #pragma unroll
            for (int r = 0; r < 4; r++)
                acc[i][j][r] = 0.0f;

    // Prefetch ALL chunks up-front: stage s holds chunk s.
    #pragma unroll
    for (int c = 0; c < NCHUNKS; c++) {
        const uint32_t dA = smem_base + (uint32_t)c * (STAGE_FLOATS * 4);
        const uint32_t dB = dA + 32768;
        // A: 2048 float4 -> smem [kt4][mt16][lane32] (mt<8 from block0)
        #pragma unroll
        for (int i = 0; i < 4; i++) {
            const int o    = tid + i * 512;        // 0..2047
            const int kt   = o >> 9;
            const int mt   = (o >> 5) & 15;
            const int ln   = o & 31;
            const float* s = (mt < 8)
                ? srcA0 + c * 4096 + ((kt * 8 + mt) * 32 + ln) * 4
                : srcA1 + c * 4096 + ((kt * 8 + (mt - 8)) * 32 + ln) * 4;
            asm volatile("cp.async.cg.shared.global [%0], [%1], 16;"
                         :: "r"(dA + (uint32_t)o * 16), "l"(s));
        }
        // B: 1024 float4 contiguous
        #pragma unroll
        for (int i = 0; i < 2; i++) {
            const int o = tid + i * 512;           // 0..1023
            asm volatile("cp.async.cg.shared.global [%0], [%1], 16;"
                         :: "r"(dB + (uint32_t)o * 16),
                            "l"(srcB + c * 4096 + o * 4));
        }
        asm volatile("cp.async.commit_group;" ::: "memory");
    }

    #pragma unroll
    for (int ch = 0; ch < NCHUNKS; ch++) {
        asm volatile("cp.async.wait_group %0;" :: "n"(0) : "memory");
        // NOTE: wait_group takes an immediate; we need (NCHUNKS-1-ch).
        // Handled below via explicit per-iteration immediates.
        __syncthreads();

        const float* As = sm + ch * STAGE_FLOATS;      // [kt][mt16][lane][4]
        const float* Bs = As + 8192;                   // [kt][nt16][lane][2]

        #pragma unroll
        for (int kt = 0; kt < 4; kt++) {
            uint32_t a[4][4], bf[4][2];
            #pragma unroll
            for (int i = 0; i < 4; i++) {
                const float* p =
                    As + ((kt * 16 + mband * 4 + i) * 32 + lane) * 4;
                asm volatile("ld.shared.v4.b32 {%0,%1,%2,%3}, [%4];"
                             : "=r"(a[i][0]), "=r"(a[i][1]),
                               "=r"(a[i][2]), "=r"(a[i][3])
                             : "l"(p));
            }
            #pragma unroll
            for (int j = 0; j < 4; j++) {
                const float* p =
                    Bs + ((kt * 16 + nband * 4 + j) * 32 + lane) * 2;
                asm volatile("ld.shared.v2.b32 {%0,%1}, [%2];"
                             : "=r"(bf[j][0]), "=r"(bf[j][1])
                             : "l"(p));
            }
            #pragma unroll
            for (int i = 0; i < 4; i++)
                #pragma unroll
                for (int j = 0; j < 4; j++) {
                    asm volatile(
                        "mma.sync.aligned.m16n8k8.row.col.f32.tf32.tf32.f32 "
                        "{%0,%1,%2,%3}, {%4,%5,%6,%7}, {%8,%9}, {%0,%1,%2,%3};"
                        : "+f"(acc[i][j][0]), "+f"(acc[i][j][1]),
                          "+f"(acc[i][j][2]), "+f"(acc[i][j][3])
                        : "r"(a[i][0]), "r"(a[i][1]),
                          "r"(a[i][2]), "r"(a[i][3]),
                          "r"(bf[j][0]), "r"(bf[j][1]));
                }
        }
    }

    // Epilogue
    const int mBase = by * TILE_M;
    const int nBase = bx * TILE_N;
    #pragma unroll
    for (int i = 0; i < 4; i++) {
        const int row0 = mBase + mband * 64 + i * 16 + g;
        #pragma unroll
        for (int j = 0; j < 4; j++) {
            const int col = nBase + nband * 32 + j * 8 + tt * 2;
            float2 lo = make_float2(acc[i][j][0], acc[i][j][1]);
            float2 hi = make_float2(acc[i][j][2], acc[i][j][3]);
            *reinterpret_cast<float2*>(Cb + (size_t)row0 * NDIM + col) = lo;
            *reinterpret_cast<float2*>(Cb + (size_t)(row0 + 8) * NDIM + col) = hi;
        }
    }
}

extern "C" void kernel_launch(void* const* d_in, const int* in_sizes, int n_in,
                              void* d_out, int out_size) {
    const float* A = (const float*)d_in[0];
    const float* B = (const float*)d_in[1];
    float* C = (float*)d_out;

    cudaFuncSetAttribute(bmm_tf32_big_kernel,
                         cudaFuncAttributeMaxDynamicSharedMemorySize, SMEM_BYTES);

    prep_a_kernel<<<4096, 256>>>(A);     // 2^20 threads
    prep_b_kernel<<<8192, 256>>>(B);     // 2^21 threads

    dim3 grid(NDIM / TILE_N, MDIM / TILE_M, BATCH);  // 32 x 16 x 8 = 4096
    bmm_tf32_big_kernel<<<grid, 512, SMEM_BYTES>>>(C);
}

// round 14
// speedup vs baseline: 1.0436x; 1.0436x over previous
#include <cuda_runtime.h>
#include <cstdint>

// Batched NT-GEMM: C[b,i,j] = sum_d A[b,i,d] * B[b,j,d]
// B=8, M=N=4096, K=128, fp32 in/out.
//
// tf32 mma.sync.m16n8k8 path.  Phase 1: prepass -> fragment-major tf32 scratch.
// Phase 2: 256x128-tile GEMM (512 thr, 1 CTA/SM), all-K prefetch into 4 smem
// stages (192KB) via cp.async with PER-CHUNK wait immediates (3,2,1,0) so
// chunk 0 computes while chunks 1-3 stream in.

#define BATCH 8
#define MDIM 4096
#define NDIM 4096
#define KDIM 128

#define TILE_M 256
#define TILE_N 128
#define NCHUNKS 4          // K chunks of 32 (4 kt-groups of 8)

// Fragment-major scratch:
// Atf: [b][M128(32)][kt(16)][mt(8)][lane(32)][r(4)]   (16.8 MB)
// Btf: [b][N128(32)][kt(16)][nt(16)][lane(32)][r(2)]  (16.8 MB)
__device__ float g_Atf[(size_t)BATCH * MDIM * KDIM];
__device__ float g_Btf[(size_t)BATCH * NDIM * KDIM];

// Smem stage: A 8192 floats [kt4][mt16][lane32][r4] (32KB)
//           + B 4096 floats [kt4][nt16][lane32][r2] (16KB) = 48KB; 4 stages.
#define STAGE_FLOATS 12288
#define SMEM_BYTES (NCHUNKS * STAGE_FLOATS * 4)   // 192 KB

__device__ __forceinline__ float f2tf32f(float f) {
    uint32_t u;
    asm("cvt.rna.tf32.f32 %0, %1;" : "=r"(u) : "f"(f));
    return __uint_as_float(u);
}

__device__ __forceinline__ uint32_t smem_u32(const void* p) {
    uint32_t a;
    asm("{ .reg .u64 t; cvta.to.shared.u64 t, %1; cvt.u32.u64 %0, t; }"
        : "=r"(a) : "l"(p));
    return a;
}

// ---------------- Prepass ----------------
__global__ __launch_bounds__(256)
void prep_a_kernel(const float* __restrict__ A) {
    const int id   = blockIdx.x * 256 + threadIdx.x;   // 0 .. 2^20-1
    const int lane = id & 31;
    const int mt   = (id >> 5) & 7;
    const int kt   = (id >> 8) & 15;
    const int M    = (id >> 12) & 31;
    const int b    = id >> 17;

    const int g  = lane >> 2;
    const int tt = lane & 3;
    const int m0 = M * 128 + mt * 16 + g;
    const int k0 = kt * 8 + tt;

    const float* src = A + ((size_t)b * MDIM + m0) * KDIM;
    float4 v;
    v.x = f2tf32f(src[k0]);
    v.y = f2tf32f(src[8 * KDIM + k0]);
    v.z = f2tf32f(src[k0 + 4]);
    v.w = f2tf32f(src[8 * KDIM + k0 + 4]);
    *reinterpret_cast<float4*>(g_Atf + (size_t)id * 4) = v;
}

__global__ __launch_bounds__(256)
void prep_b_kernel(const float* __restrict__ B) {
    const int id   = blockIdx.x * 256 + threadIdx.x;   // 0 .. 2^21-1
    const int lane = id & 31;
    const int nt   = (id >> 5) & 15;
    const int kt   = (id >> 9) & 15;
    const int N    = (id >> 13) & 31;
    const int b    = id >> 18;

    const int g  = lane >> 2;
    const int tt = lane & 3;
    const int n0 = N * 128 + nt * 8 + g;
    const int k0 = kt * 8 + tt;

    const float* src = B + ((size_t)b * NDIM + n0) * KDIM;
    float2 v;
    v.x = f2tf32f(src[k0]);
    v.y = f2tf32f(src[k0 + 4]);
    *reinterpret_cast<float2*>(g_Btf + (size_t)id * 2) = v;
}

// ---------------- Main GEMM: 256x128 tile, 512 threads, 1 CTA/SM ----------------
__global__ __launch_bounds__(512, 1)
void bmm_tf32_big_kernel(float* __restrict__ C) {
    extern __shared__ float sm[];
    const uint32_t smem_base = smem_u32(sm);

    const int tid  = threadIdx.x;
    const int lane = tid & 31;
    const int wid  = tid >> 5;          // 0..15
    const int g    = lane >> 2;
    const int tt   = lane & 3;

    const int b  = blockIdx.z;
    const int by = blockIdx.y;          // M256 tile (0..15)
    const int bx = blockIdx.x;          // N128 tile (0..31)

    const float* srcA0 = g_Atf + (size_t)((b * 32 + by * 2) * 16) * 1024;
    const float* srcA1 = srcA0 + 16384;
    const float* srcB  = g_Btf + (size_t)((b * 32 + bx) * 16) * 1024;
    float* Cb = C + (size_t)b * MDIM * NDIM;

    const int mband = wid >> 2;         // 0..3  (64-row band)
    const int nband = wid & 3;          // 0..3  (32-col band)

    float acc[4][4][4];
    #pragma unroll
    for (int i = 0; i < 4; i++)
        #pragma unroll
        for (int j = 0; j < 4; j++)
            #pragma unroll
            for (int r = 0; r < 4; r++)
                acc[i][j][r] = 0.0f;

    // Prefetch ALL chunks up-front: stage s holds chunk s, one commit each.
    #pragma unroll
    for (int c = 0; c < NCHUNKS; c++) {
        const uint32_t dA = smem_base + (uint32_t)c * (STAGE_FLOATS * 4);
        const uint32_t dB = dA + 32768;
        #pragma unroll
        for (int i = 0; i < 4; i++) {
            const int o    = tid + i * 512;        // 0..2047
            const int kt   = o >> 9;
            const int mt   = (o >> 5) & 15;
            const int ln   = o & 31;
            const float* s = (mt < 8)
                ? srcA0 + c * 4096 + ((kt * 8 + mt) * 32 + ln) * 4
                : srcA1 + c * 4096 + ((kt * 8 + (mt - 8)) * 32 + ln) * 4;
            asm volatile("cp.async.cg.shared.global [%0], [%1], 16;"
                         :: "r"(dA + (uint32_t)o * 16), "l"(s));
        }
        #pragma unroll
        for (int i = 0; i < 2; i++) {
            const int o = tid + i * 512;           // 0..1023
            asm volatile("cp.async.cg.shared.global [%0], [%1], 16;"
                         :: "r"(dB + (uint32_t)o * 16),
                            "l"(srcB + c * 4096 + o * 4));
        }
        asm volatile("cp.async.commit_group;" ::: "memory");
    }

    #pragma unroll
    for (int ch = 0; ch < NCHUNKS; ch++) {
        // Wait until chunk ch's group has landed (groups complete in order).
        if (ch == 0)      asm volatile("cp.async.wait_group 3;" ::: "memory");
        else if (ch == 1) asm volatile("cp.async.wait_group 2;" ::: "memory");
        else if (ch == 2) asm volatile("cp.async.wait_group 1;" ::: "memory");
        else              asm volatile("cp.async.wait_group 0;" ::: "memory");
        __syncthreads();

        const float* As = sm + ch * STAGE_FLOATS;      // [kt][mt16][lane][4]
        const float* Bs = As + 8192;                   // [kt][nt16][lane][2]

        #pragma unroll
        for (int kt = 0; kt < 4; kt++) {
            uint32_t a[4][4], bf[4][2];
            #pragma unroll
            for (int i = 0; i < 4; i++) {
                const float* p =
                    As + ((kt * 16 + mband * 4 + i) * 32 + lane) * 4;
                asm volatile("ld.shared.v4.b32 {%0,%1,%2,%3}, [%4];"
                             : "=r"(a[i][0]), "=r"(a[i][1]),
                               "=r"(a[i][2]), "=r"(a[i][3])
                             : "l"(p));
            }
            #pragma unroll
            for (int j = 0; j < 4; j++) {
                const float* p =
                    Bs + ((kt * 16 + nband * 4 + j) * 32 + lane) * 2;
                asm volatile("ld.shared.v2.b32 {%0,%1}, [%2];"
                             : "=r"(bf[j][0]), "=r"(bf[j][1])
                             : "l"(p));
            }
            #pragma unroll
            for (int i = 0; i < 4; i++)
                #pragma unroll
                for (int j = 0; j < 4; j++) {
                    asm volatile(
                        "mma.sync.aligned.m16n8k8.row.col.f32.tf32.tf32.f32 "
                        "{%0,%1,%2,%3}, {%4,%5,%6,%7}, {%8,%9}, {%0,%1,%2,%3};"
                        : "+f"(acc[i][j][0]), "+f"(acc[i][j][1]),
                          "+f"(acc[i][j][2]), "+f"(acc[i][j][3])
                        : "r"(a[i][0]), "r"(a[i][1]),
                          "r"(a[i][2]), "r"(a[i][3]),
                          "r"(bf[j][0]), "r"(bf[j][1]));
                }
        }
    }

    // Epilogue
    const int mBase = by * TILE_M;
    const int nBase = bx * TILE_N;
    #pragma unroll
    for (int i = 0; i < 4; i++) {
        const int row0 = mBase + mband * 64 + i * 16 + g;
        #pragma unroll
        for (int j = 0; j < 4; j++) {
            const int col = nBase + nband * 32 + j * 8 + tt * 2;
            float2 lo = make_float2(acc[i][j][0], acc[i][j][1]);
            float2 hi = make_float2(acc[i][j][2], acc[i][j][3]);
            *reinterpret_cast<float2*>(Cb + (size_t)row0 * NDIM + col) = lo;
            *reinterpret_cast<float2*>(Cb + (size_t)(row0 + 8) * NDIM + col) = hi;
        }
    }
}

extern "C" void kernel_launch(void* const* d_in, const int* in_sizes, int n_in,
                              void* d_out, int out_size) {
    const float* A = (const float*)d_in[0];
    const float* B = (const float*)d_in[1];
    float* C = (float*)d_out;

    cudaFuncSetAttribute(bmm_tf32_big_kernel,
                         cudaFuncAttributeMaxDynamicSharedMemorySize, SMEM_BYTES);

    prep_a_kernel<<<4096, 256>>>(A);     // 2^20 threads
    prep_b_kernel<<<8192, 256>>>(B);     // 2^21 threads

    dim3 grid(NDIM / TILE_N, MDIM / TILE_M, BATCH);  // 32 x 16 x 8 = 4096
    bmm_tf32_big_kernel<<<grid, 512, SMEM_BYTES>>>(C);
}

// round 16
// speedup vs baseline: 1.2463x; 1.1942x over previous
#include <cuda_runtime.h>
#include <cstdint>

// Batched NT-GEMM: C[b,i,j] = sum_d A[b,i,d] * B[b,j,d]
// B=8, M=N=4096, K=128, fp32 in/out.
//
// tf32 mma.sync.m16n8k8.  Phase 1: fused prepass -> fragment-major tf32 scratch.
// Phase 2: per CTA, B block (full K=128, 64KB) resident in smem; TWO stacked
// 128x128 A tiles (by-pair) stream through 3 A-stages (16KB each) via cp.async.
// 256 thr, 2 CTA/SM, 112KB smem/CTA.  Operand L2 traffic 1.07GB -> 786MB.

#define BATCH 8
#define MDIM 4096
#define NDIM 4096
#define KDIM 128

// Fragment-major scratch:
// Atf: [b][M128(32)][kt(16)][mt(8)][lane(32)][r(4)]   (16.8 MB)
// Btf: [b][N128(32)][kt(16)][nt(16)][lane(32)][r(2)]  (16.8 MB)
__device__ float g_Atf[(size_t)BATCH * MDIM * KDIM];
__device__ float g_Btf[(size_t)BATCH * NDIM * KDIM];

// Smem (floats): B[16384] then 3 A stages of 4096 each = 28672 floats = 112KB
#define SMEM_B_FLOATS 16384
#define A_STAGE_FLOATS 4096
#define SMEM_BYTES ((SMEM_B_FLOATS + 3 * A_STAGE_FLOATS) * 4)   // 114688

__device__ __forceinline__ float f2tf32f(float f) {
    uint32_t u;
    asm("cvt.rna.tf32.f32 %0, %1;" : "=r"(u) : "f"(f));
    return __uint_as_float(u);
}

__device__ __forceinline__ uint32_t smem_u32(const void* p) {
    uint32_t a;
    asm("{ .reg .u64 t; cvta.to.shared.u64 t, %1; cvt.u32.u64 %0, t; }"
        : "=r"(a) : "l"(p));
    return a;
}

// ---------------- Fused prepass: A then B ----------------
__global__ __launch_bounds__(256)
void prep_ab_kernel(const float* __restrict__ A, const float* __restrict__ B) {
    const int id = blockIdx.x * 256 + threadIdx.x;

    if (id < (1 << 20)) {
        // A fragment: [b][M(5b)][kt(4b)][mt(3b)][lane(5b)] -> one float4
        const int lane = id & 31;
        const int mt   = (id >> 5) & 7;
        const int kt   = (id >> 8) & 15;
        const int M    = (id >> 12) & 31;
        const int b    = id >> 17;

        const int g  = lane >> 2;
        const int tt = lane & 3;
        const int m0 = M * 128 + mt * 16 + g;
        const int k0 = kt * 8 + tt;

        const float* src = A + ((size_t)b * MDIM + m0) * KDIM;
        float4 v;
        v.x = f2tf32f(src[k0]);
        v.y = f2tf32f(src[8 * KDIM + k0]);
        v.z = f2tf32f(src[k0 + 4]);
        v.w = f2tf32f(src[8 * KDIM + k0 + 4]);
        *reinterpret_cast<float4*>(g_Atf + (size_t)id * 4) = v;
    } else {
        // B fragment: [b][N(5b)][kt(4b)][nt(4b)][lane(5b)] -> one float2
        const int idb  = id - (1 << 20);      // 0 .. 2^21-1
        const int lane = idb & 31;
        const int nt   = (idb >> 5) & 15;
        const int kt   = (idb >> 9) & 15;
        const int N    = (idb >> 13) & 31;    // FIXED (was >>12)
        const int b    = idb >> 18;           // FIXED (was >>17)

        const int g  = lane >> 2;
        const int tt = lane & 3;
        const int n0 = N * 128 + nt * 8 + g;
        const int k0 = kt * 8 + tt;

        const float* src = B + ((size_t)b * NDIM + n0) * KDIM;
        float2 v;
        v.x = f2tf32f(src[k0]);
        v.y = f2tf32f(src[k0 + 4]);
        *reinterpret_cast<float2*>(g_Btf + (size_t)idb * 2) = v;
    }
}

// ---------------- Main GEMM: B-resident, 2 stacked A tiles ----------------
__global__ __launch_bounds__(256, 2)
void bmm_tf32_breuse_kernel(float* __restrict__ C) {
    extern __shared__ float sm[];
    const uint32_t smem_base = smem_u32(sm);

    const int tid  = threadIdx.x;
    const int lane = tid & 31;
    const int wid  = tid >> 5;
    const int g    = lane >> 2;
    const int tt   = lane & 3;

    const int b  = blockIdx.z;
    const int bp = blockIdx.y;          // by-pair (0..15) -> rows [bp*256, +256)
    const int bx = blockIdx.x;          // N128 tile (0..31)

    const float* srcA0 = g_Atf + (size_t)((b * 32 + bp * 2) * 16) * 1024;
    const float* srcB  = g_Btf + (size_t)((b * 32 + bx) * 16) * 1024;
    float* Cb = C + (size_t)b * MDIM * NDIM;

    const int mband = wid >> 2;         // 0..1
    const int nband = wid & 3;          // 0..3

    float acc[4][4][4];
    #pragma unroll
    for (int i = 0; i < 4; i++)
        #pragma unroll
        for (int j = 0; j < 4; j++)
            #pragma unroll
            for (int r = 0; r < 4; r++)
                acc[i][j][r] = 0.0f;

    // A chunk prefetch: global chunk gc (0..7) -> stage s.  tile = gc>>2, c = gc&3.
    auto prefetchA = [&](int s, int gc) {
        const float* src = srcA0 + (size_t)(gc >> 2) * 16384 + (gc & 3) * 4096;
        const uint32_t dst =
            smem_base + (uint32_t)(SMEM_B_FLOATS + s * A_STAGE_FLOATS) * 4;
        #pragma unroll
        for (int i = 0; i < 4; i++) {
            const int o = tid + i * 256;           // float4 idx 0..1023
            asm volatile("cp.async.cg.shared.global [%0], [%1], 16;"
                         :: "r"(dst + (uint32_t)o * 16), "l"(src + o * 4));
        }
    };

    // Prologue: A chunk0 (P0), B full (P1), A chunk1 (P2)
    prefetchA(0, 0);
    asm volatile("cp.async.commit_group;" ::: "memory");
    #pragma unroll
    for (int i = 0; i < 16; i++) {
        const int o = tid + i * 256;               // float4 idx 0..4095
        asm volatile("cp.async.cg.shared.global [%0], [%1], 16;"
                     :: "r"(smem_base + (uint32_t)o * 16), "l"(srcB + o * 4));
    }
    asm volatile("cp.async.commit_group;" ::: "memory");
    prefetchA(1, 1);
    asm volatile("cp.async.commit_group;" ::: "memory");

    const int mBaseCta = bp * 256;
    const int nBase = bx * 128;

    #pragma unroll
    for (int gc = 0; gc < 8; gc++) {
        if (gc < 7) asm volatile("cp.async.wait_group 1;" ::: "memory");
        else        asm volatile("cp.async.wait_group 0;" ::: "memory");
        __syncthreads();

        // Hoisted prefetch: chunk gc+2 into stage (gc+2)%3 (held gc-1, done).
        if (gc < 6) {
            prefetchA((gc + 2) % 3, gc + 2);
            asm volatile("cp.async.commit_group;" ::: "memory");
        }

        const float* As = sm + SMEM_B_FLOATS + (gc % 3) * A_STAGE_FLOATS;
        const int cLoc = gc & 3;                   // K-chunk within tile

        #pragma unroll
        for (int ktl = 0; ktl < 4; ktl++) {
            const int ktg = cLoc * 4 + ktl;        // global kt for B
            uint32_t a[4][4], bf[4][2];
            #pragma unroll
            for (int i = 0; i < 4; i++) {
                const float* p =
                    As + ((ktl * 8 + mband * 4 + i) * 32 + lane) * 4;
                asm volatile("ld.shared.v4.b32 {%0,%1,%2,%3}, [%4];"
                             : "=r"(a[i][0]), "=r"(a[i][1]),
                               "=r"(a[i][2]), "=r"(a[i][3])
                             : "l"(p));
            }
            #pragma unroll
            for (int j = 0; j < 4; j++) {
                const float* p =
                    sm + ((ktg * 16 + nband * 4 + j) * 32 + lane) * 2;
                asm volatile("ld.shared.v2.b32 {%0,%1}, [%2];"
                             : "=r"(bf[j][0]), "=r"(bf[j][1])
                             : "l"(p));
            }
            #pragma unroll
            for (int i = 0; i < 4; i++)
                #pragma unroll
                for (int j = 0; j < 4; j++) {
                    asm volatile(
                        "mma.sync.aligned.m16n8k8.row.col.f32.tf32.tf32.f32 "
                        "{%0,%1,%2,%3}, {%4,%5,%6,%7}, {%8,%9}, {%0,%1,%2,%3};"
                        : "+f"(acc[i][j][0]), "+f"(acc[i][j][1]),
                          "+f"(acc[i][j][2]), "+f"(acc[i][j][3])
                        : "r"(a[i][0]), "r"(a[i][1]),
                          "r"(a[i][2]), "r"(a[i][3]),
                          "r"(bf[j][0]), "r"(bf[j][1]));
                }
        }

        // Tile 0 complete after chunk 3: store it, reset accumulators.
        if (gc == 3) {
            #pragma unroll
            for (int i = 0; i < 4; i++) {
                const int row0 = mBaseCta + mband * 64 + i * 16 + g;
                #pragma unroll
                for (int j = 0; j < 4; j++) {
                    const int col = nBase + nband * 32 + j * 8 + tt * 2;
                    float2 lo = make_float2(acc[i][j][0], acc[i][j][1]);
                    float2 hi = make_float2(acc[i][j][2], acc[i][j][3]);
                    *reinterpret_cast<float2*>(
                        Cb + (size_t)row0 * NDIM + col) = lo;
                    *reinterpret_cast<float2*>(
                        Cb + (size_t)(row0 + 8) * NDIM + col) = hi;
                    acc[i][j][0] = 0.0f; acc[i][j][1] = 0.0f;
                    acc[i][j][2] = 0.0f; acc[i][j][3] = 0.0f;
                }
            }
        }
    }

    // Tile 1 epilogue
    #pragma unroll
    for (int i = 0; i < 4; i++) {
        const int row0 = mBaseCta + 128 + mband * 64 + i * 16 + g;
        #pragma unroll
        for (int j = 0; j < 4; j++) {
            const int col = nBase + nband * 32 + j * 8 + tt * 2;
            float2 lo = make_float2(acc[i][j][0], acc[i][j][1]);
            float2 hi = make_float2(acc[i][j][2], acc[i][j][3]);
            *reinterpret_cast<float2*>(Cb + (size_t)row0 * NDIM + col) = lo;
            *reinterpret_cast<float2*>(Cb + (size_t)(row0 + 8) * NDIM + col) = hi;
        }
    }
}

extern "C" void kernel_launch(void* const* d_in, const int* in_sizes, int n_in,
                              void* d_out, int out_size) {
    const float* A = (const float*)d_in[0];
    const float* B = (const float*)d_in[1];
    float* C = (float*)d_out;

    cudaFuncSetAttribute(bmm_tf32_breuse_kernel,
                         cudaFuncAttributeMaxDynamicSharedMemorySize, SMEM_BYTES);

    prep_ab_kernel<<<12288, 256>>>(A, B);   // 2^20 A-frag + 2^21 B-frag threads

    dim3 grid(NDIM / 128, MDIM / 256, BATCH);  // 32 x 16 x 8 = 4096
    bmm_tf32_breuse_kernel<<<grid, 256, SMEM_BYTES>>>(C);
}